// round 1
// baseline (speedup 1.0000x reference)
#include <cuda_runtime.h>
#include <cstdint>

#define BB 8
#define NN 2000
#define EE 20
#define HH 128

// Scratch for Vx = x@Wv + bv  (8*2000*128 floats = 8.2 MB). __device__ global:
// allocation-free per harness rules.
__device__ float g_Vx[BB * NN * HH];

typedef unsigned long long u64;

// Packed fp32x2 FMA (Blackwell). ptxas never emits FFMA2 from C++; this is the
// only way to get 2x fp32 FMA throughput per issue slot.
__device__ __forceinline__ u64 ffma2(u64 a, u64 b, u64 c) {
    u64 d;
    asm("fma.rn.f32x2 %0, %1, %2, %3;" : "=l"(d) : "l"(a), "l"(b), "l"(c));
    return d;
}

__device__ __forceinline__ float2 unpack2(u64 v) {
    float2 r;
    asm("mov.b64 {%0, %1}, %2;" : "=f"(r.x), "=f"(r.y) : "l"(v));
    return r;
}

// ---------------------------------------------------------------------------
// Kernel A: Ux = x@Wu + bu -> out ;  Vx = x@Wv + bv -> g_Vx
// 256 threads: 2 row-slots x 128 channel-threads.
// smem: Wu and Wv pair-interleaved over k: WP[kp*128 + j] = (W[2kp][j], W[2kp+1][j])
// ---------------------------------------------------------------------------
__global__ void __launch_bounds__(256, 1) kA(
    const float* __restrict__ x, const float* __restrict__ Wu,
    const float* __restrict__ bu, const float* __restrict__ Wv,
    const float* __restrict__ bv, float* __restrict__ out)
{
    extern __shared__ float sm[];
    float* sWuP = sm;              // 16384 floats
    float* sWvP = sm + 16384;      // 16384 floats
    float* sx   = sm + 32768;      // 2 * 128 floats
    const int tid = threadIdx.x;

    // Build pair-interleaved weight copies (coalesced global reads).
    for (int idx = tid; idx < 8192; idx += 256) {
        int kp = idx >> 7, j = idx & 127;
        sWuP[2 * idx]     = Wu[(2 * kp) * HH + j];
        sWuP[2 * idx + 1] = Wu[(2 * kp + 1) * HH + j];
        sWvP[2 * idx]     = Wv[(2 * kp) * HH + j];
        sWvP[2 * idx + 1] = Wv[(2 * kp + 1) * HH + j];
    }
    const int slot = tid >> 7;     // 0..1
    const int j = tid & 127;
    const float buj = bu[j];
    const float bvj = bv[j];
    const u64* wU = (const u64*)sWuP;
    const u64* wV = (const u64*)sWvP;
    __syncthreads();

    const int nGroups = (BB * NN) / 2;   // 8000
    for (int g = blockIdx.x; g < nGroups; g += gridDim.x) {
        const int row = g * 2 + slot;
        sx[slot * HH + j] = x[(size_t)row * HH + j];
        __syncthreads();

        u64 aU = 0ull, aV = 0ull;
        const float* xr = sx + slot * HH;
        #pragma unroll
        for (int kt = 0; kt < 32; kt++) {
            ulonglong2 xv = *(const ulonglong2*)(xr + kt * 4);   // k..k+3, packed pairs
            u64 wu0 = wU[(2 * kt) * HH + j];
            u64 wu1 = wU[(2 * kt + 1) * HH + j];
            u64 wv0 = wV[(2 * kt) * HH + j];
            u64 wv1 = wV[(2 * kt + 1) * HH + j];
            aU = ffma2(xv.x, wu0, aU);
            aU = ffma2(xv.y, wu1, aU);
            aV = ffma2(xv.x, wv0, aV);
            aV = ffma2(xv.y, wv1, aV);
        }
        float2 pu = unpack2(aU);
        float2 pv = unpack2(aV);
        out[(size_t)row * HH + j]  = pu.x + pu.y + buj;
        g_Vx[(size_t)row * HH + j] = pv.x + pv.y + bvj;
        __syncthreads();
    }
}

// ---------------------------------------------------------------------------
// Kernel B: per node n:
//   logits[i][j] = (e_rows @ We + be)   (20 x 128)
//   softmax over i per channel j, gather Vx rows per edge_index, weighted sum,
//   out[n][j] += result.
// 256 threads: 2 node-slots x 128 channel-threads.
// ---------------------------------------------------------------------------
__global__ void __launch_bounds__(256, 2) kB(
    const float* __restrict__ e, const float* __restrict__ We,
    const float* __restrict__ be, const int* __restrict__ edge_index,
    float* __restrict__ out)
{
    extern __shared__ float sm[];
    float* sWeP = sm;                          // 16384 floats (pair-interleaved We)
    float* sE   = sm + 16384;                  // 2 slots * 20*128 floats
    int*   sIdx = (int*)(sm + 16384 + 5120);   // 2 slots * 32 ints

    const int tid = threadIdx.x;
    for (int idx = tid; idx < 8192; idx += 256) {
        int kp = idx >> 7, j = idx & 127;
        sWeP[2 * idx]     = We[(2 * kp) * HH + j];
        sWeP[2 * idx + 1] = We[(2 * kp + 1) * HH + j];
    }
    const int slot = tid >> 7;       // 0..1
    const int lt = tid & 127;        // channel j within slot
    const int j = lt;
    const float bej = be[j];
    const u64* wE = (const u64*)sWeP;
    __syncthreads();

    const int nGroups = (BB * NN) / 2;   // 8000
    for (int g = blockIdx.x; g < nGroups; g += gridDim.x) {
        const int node = g * 2 + slot;               // 0..15999  (= b*N + n)
        const size_t eBase = (size_t)node * (EE * HH);

        // Cooperative load of this node's 20 contiguous edge rows (10 KB).
        float4* sE4 = (float4*)(sE + slot * (EE * HH));
        const float4* ge4 = (const float4*)(e + eBase);
        #pragma unroll
        for (int q = 0; q < 5; q++) sE4[lt + 128 * q] = ge4[lt + 128 * q];
        if (lt < EE) sIdx[slot * 32 + lt] = edge_index[(size_t)node * EE + lt];
        __syncthreads();

        u64 acc[EE];
        #pragma unroll
        for (int i = 0; i < EE; i++) acc[i] = 0ull;

        const float* eS = sE + slot * (EE * HH);
        #pragma unroll 2
        for (int kt = 0; kt < 32; kt++) {
            u64 w0 = wE[(2 * kt) * HH + j];          // (We[4kt][j],   We[4kt+1][j])
            u64 w1 = wE[(2 * kt + 1) * HH + j];      // (We[4kt+2][j], We[4kt+3][j])
            #pragma unroll
            for (int i = 0; i < EE; i++) {
                ulonglong2 ev = *(const ulonglong2*)(eS + i * HH + kt * 4);  // broadcast
                acc[i] = ffma2(ev.x, w0, acc[i]);
                acc[i] = ffma2(ev.y, w1, acc[i]);
            }
        }

        float logit[EE];
        #pragma unroll
        for (int i = 0; i < EE; i++) {
            float2 p = unpack2(acc[i]);
            logit[i] = p.x + p.y + bej;
        }
        float m = logit[0];
        #pragma unroll
        for (int i = 1; i < EE; i++) m = fmaxf(m, logit[i]);
        float s = 0.f;
        #pragma unroll
        for (int i = 0; i < EE; i++) {
            float ex = __expf(logit[i] - m);
            logit[i] = ex;
            s += ex;
        }

        const int bBase = (node / NN) * NN;          // b * N
        float accO = 0.f;
        #pragma unroll
        for (int i = 0; i < EE; i++) {
            int r = sIdx[slot * 32 + i];
            accO += logit[i] * g_Vx[(size_t)(bBase + r) * HH + j];
        }
        out[(size_t)node * HH + j] += accO * __fdividef(1.f, s);
        __syncthreads();
    }
}

// ---------------------------------------------------------------------------
extern "C" void kernel_launch(void* const* d_in, const int* in_sizes, int n_in,
                              void* d_out, int out_size)
{
    const float* x          = (const float*)d_in[0];
    const float* e          = (const float*)d_in[1];
    const float* Wu         = (const float*)d_in[2];
    const float* bu         = (const float*)d_in[3];
    const float* Wv         = (const float*)d_in[4];
    const float* bv         = (const float*)d_in[5];
    const float* We         = (const float*)d_in[6];
    const float* be         = (const float*)d_in[7];
    const int*   edge_index = (const int*)d_in[8];
    float* out = (float*)d_out;

    const int smemA = (16384 + 16384 + 256) * 4;   // 132096 B
    const int smemB = (16384 + 5120 + 64) * 4;     // 86272 B
    cudaFuncSetAttribute(kA, cudaFuncAttributeMaxDynamicSharedMemorySize, smemA);
    cudaFuncSetAttribute(kB, cudaFuncAttributeMaxDynamicSharedMemorySize, smemB);

    kA<<<152, 256, smemA>>>(x, Wu, bu, Wv, bv, out);
    kB<<<304, 256, smemB>>>(e, We, be, edge_index, out);
}

// round 3
// speedup vs baseline: 2.8945x; 2.8945x over previous
#include <cuda_runtime.h>
#include <cuda_bf16.h>
#include <cstdint>

#define BB 8
#define NN 2000
#define EE 20
#define HH 128
#define TNODES 4
#define TROWS 80                 // 4 nodes * 20 edges per CTA tile
#define NTILES 4000              // 16000 nodes / 4

// kB smem layout (bytes)
#define SWH_OFF   0              // We hi  bf16, swizzled rows of 256B: 128*256 = 32768
#define SWL_OFF   32768          // We lo
#define SA_OFF    65536          // A (e-tile) double buffer: 2 * 40960
#define ABUF_B    40960          // one buffer = hi(20480) + lo(20480)
#define ALO       20480
#define SLOG_OFF  147456         // logits 80 x 132 fp32 = 42240
#define LSTRIDE   132
#define SIDX_OFF  189696         // 80 ints
#define SMEMB     190016

__device__ float g_Vx[BB * NN * HH];

typedef unsigned long long u64;

// ---------------------------------------------------------------- helpers
__device__ __forceinline__ u64 ffma2(u64 a, u64 b, u64 c) {
    u64 d;
    asm("fma.rn.f32x2 %0, %1, %2, %3;" : "=l"(d) : "l"(a), "l"(b), "l"(c));
    return d;
}
__device__ __forceinline__ float2 unpack2(u64 v) {
    float2 r;
    asm("mov.b64 {%0, %1}, %2;" : "=f"(r.x), "=f"(r.y) : "l"(v));
    return r;
}
__device__ __forceinline__ uint32_t smem_u32(const void* p) {
    uint32_t a;
    asm("{ .reg .u64 t; cvta.to.shared.u64 t, %1; cvt.u32.u64 %0, t; }" : "=r"(a) : "l"(p));
    return a;
}
// pack two fp32 into bf16x2: low half = bf16(lo), high half = bf16(hi)
__device__ __forceinline__ uint32_t pack_bf16(float lo, float hi) {
    uint32_t r;
    asm("cvt.rn.bf16x2.f32 %0, %1, %2;" : "=r"(r) : "f"(hi), "f"(lo));
    return r;
}
__device__ __forceinline__ void ldsm4(uint32_t addr, uint32_t* r) {
    asm volatile("ldmatrix.sync.aligned.m8n8.x4.shared.b16 {%0,%1,%2,%3}, [%4];"
                 : "=r"(r[0]), "=r"(r[1]), "=r"(r[2]), "=r"(r[3]) : "r"(addr));
}
__device__ __forceinline__ void ldsm4t(uint32_t addr, uint32_t* r) {
    asm volatile("ldmatrix.sync.aligned.m8n8.x4.trans.shared.b16 {%0,%1,%2,%3}, [%4];"
                 : "=r"(r[0]), "=r"(r[1]), "=r"(r[2]), "=r"(r[3]) : "r"(addr));
}
__device__ __forceinline__ void mma16816(float* d, const uint32_t* a, uint32_t b0, uint32_t b1) {
    asm volatile("mma.sync.aligned.m16n8k16.row.col.f32.bf16.bf16.f32 "
                 "{%0,%1,%2,%3}, {%4,%5,%6,%7}, {%8,%9}, {%0,%1,%2,%3};"
                 : "+f"(d[0]), "+f"(d[1]), "+f"(d[2]), "+f"(d[3])
                 : "r"(a[0]), "r"(a[1]), "r"(a[2]), "r"(a[3]), "r"(b0), "r"(b1));
}

// ---------------------------------------------------------------------------
// Kernel A: Ux = x@Wu + bu -> out ;  Vx = x@Wv + bv -> g_Vx  (scalar FFMA2)
// ---------------------------------------------------------------------------
__global__ void __launch_bounds__(256, 1) kA(
    const float* __restrict__ x, const float* __restrict__ Wu,
    const float* __restrict__ bu, const float* __restrict__ Wv,
    const float* __restrict__ bv, float* __restrict__ out)
{
    extern __shared__ __align__(1024) float smA[];
    float* sWuP = smA;              // 16384 floats, pair-interleaved over k
    float* sWvP = smA + 16384;
    float* sx   = smA + 32768;      // 16 * 128 floats
    const int tid = threadIdx.x;

    for (int idx = tid; idx < 8192; idx += 256) {
        int kp = idx >> 7, j = idx & 127;
        sWuP[2 * idx]     = Wu[(2 * kp) * HH + j];
        sWuP[2 * idx + 1] = Wu[(2 * kp + 1) * HH + j];
        sWvP[2 * idx]     = Wv[(2 * kp) * HH + j];
        sWvP[2 * idx + 1] = Wv[(2 * kp + 1) * HH + j];
    }
    const int half = tid >> 7;
    const int j = tid & 127;
    const float buj = bu[j];
    const float bvj = bv[j];
    const u64* wU = (const u64*)sWuP;
    const u64* wV = (const u64*)sWvP;
    __syncthreads();

    const int nGroups = (BB * NN) / 16;   // 1000
    for (int g = blockIdx.x; g < nGroups; g += gridDim.x) {
        const float4* xs = (const float4*)(x + (size_t)g * 16 * HH);
        float4* sx4 = (float4*)sx;
        sx4[tid] = xs[tid];
        sx4[tid + 256] = xs[tid + 256];
        __syncthreads();

        u64 aU[8], aV[8];
        #pragma unroll
        for (int r = 0; r < 8; r++) { aU[r] = 0ull; aV[r] = 0ull; }
        const float* xr = sx + half * 8 * HH;
        #pragma unroll 4
        for (int kt = 0; kt < 32; kt++) {
            u64 wu0 = wU[(2 * kt) * HH + j];
            u64 wu1 = wU[(2 * kt + 1) * HH + j];
            u64 wv0 = wV[(2 * kt) * HH + j];
            u64 wv1 = wV[(2 * kt + 1) * HH + j];
            #pragma unroll
            for (int r = 0; r < 8; r++) {
                ulonglong2 xv = *(const ulonglong2*)(xr + r * HH + kt * 4);
                aU[r] = ffma2(xv.x, wu0, aU[r]);
                aU[r] = ffma2(xv.y, wu1, aU[r]);
                aV[r] = ffma2(xv.x, wv0, aV[r]);
                aV[r] = ffma2(xv.y, wv1, aV[r]);
            }
        }
        #pragma unroll
        for (int r = 0; r < 8; r++) {
            int row = g * 16 + half * 8 + r;
            float2 pu = unpack2(aU[r]);
            float2 pv = unpack2(aV[r]);
            out[(size_t)row * HH + j]  = pu.x + pu.y + buj;
            g_Vx[(size_t)row * HH + j] = pv.x + pv.y + bvj;
        }
        __syncthreads();
    }
}

// ---------------------------------------------------------------------------
// Kernel B: logits via mma.sync bf16 3-term split, then softmax + gather.
// ---------------------------------------------------------------------------

// Convert 8 consecutive fp32 (chunk ch of the tile: row = ch/16, k-chunk = ch%16)
// into bf16 hi/lo 16B chunks and store swizzled.
__device__ __forceinline__ void cvtStoreA(char* smem, int buf, int ch,
                                          float4 v0, float4 v1) {
    int row = ch >> 4, c = ch & 15;
    uint32_t sw = ((uint32_t)row << 8) + (((uint32_t)(c ^ (row & 7))) << 4);
    float f[8] = {v0.x, v0.y, v0.z, v0.w, v1.x, v1.y, v1.z, v1.w};
    uint32_t h[4], l[4];
    #pragma unroll
    for (int m = 0; m < 4; m++) {
        uint32_t hp = pack_bf16(f[2 * m], f[2 * m + 1]);
        float hf0 = __uint_as_float(hp << 16);
        float hf1 = __uint_as_float(hp & 0xffff0000u);
        h[m] = hp;
        l[m] = pack_bf16(f[2 * m] - hf0, f[2 * m + 1] - hf1);
    }
    char* d = smem + SA_OFF + buf * ABUF_B;
    *(uint4*)(d + sw)       = make_uint4(h[0], h[1], h[2], h[3]);
    *(uint4*)(d + ALO + sw) = make_uint4(l[0], l[1], l[2], l[3]);
}

__device__ __forceinline__ void loadTileDirect(char* smem, int buf,
                                               const float* __restrict__ e, int tile) {
    const float4* src = (const float4*)(e + (size_t)tile * TROWS * HH);
    const int tid = threadIdx.x;
    #pragma unroll
    for (int q = 0; q < 5; q++) {
        int ch = tid + 256 * q;              // 0..1279
        float4 v0 = src[ch * 2];
        float4 v1 = src[ch * 2 + 1];
        cvtStoreA(smem, buf, ch, v0, v1);
    }
}

__global__ void __launch_bounds__(256, 1) kB(
    const float* __restrict__ e, const float* __restrict__ We,
    const int* __restrict__ edge_index, float* __restrict__ out)
{
    extern __shared__ __align__(1024) char smem[];
    const uint32_t sb = smem_u32(smem);
    float* sLog = (float*)(smem + SLOG_OFF);
    int*   sIdx = (int*)(smem + SIDX_OFF);
    const int tid = threadIdx.x;
    const int w = tid >> 5;
    const int l = tid & 31;

    // Build We hi/lo bf16 swizzled tiles (rows = k, 256B each).
    #pragma unroll
    for (int q = 0; q < 8; q++) {
        int ch = tid + 256 * q;              // 0..2047
        int row = ch >> 4, c = ch & 15;
        uint32_t sw = ((uint32_t)row << 8) + (((uint32_t)(c ^ (row & 7))) << 4);
        const float4* srcw = (const float4*)(We + (size_t)row * HH + c * 8);
        float4 v0 = srcw[0], v1 = srcw[1];
        float f[8] = {v0.x, v0.y, v0.z, v0.w, v1.x, v1.y, v1.z, v1.w};
        uint32_t h[4], lo[4];
        #pragma unroll
        for (int m = 0; m < 4; m++) {
            uint32_t hp = pack_bf16(f[2 * m], f[2 * m + 1]);
            float hf0 = __uint_as_float(hp << 16);
            float hf1 = __uint_as_float(hp & 0xffff0000u);
            h[m] = hp;
            lo[m] = pack_bf16(f[2 * m] - hf0, f[2 * m + 1] - hf1);
        }
        *(uint4*)(smem + SWH_OFF + sw) = make_uint4(h[0], h[1], h[2], h[3]);
        *(uint4*)(smem + SWL_OFF + sw) = make_uint4(lo[0], lo[1], lo[2], lo[3]);
    }

    // Per-lane ldmatrix row/chunk components (same form for A and B.trans).
    const int lrow = (l & 7) + ((l >> 3) & 1) * 8;   // 0..15
    const int lchk = l >> 4;                          // 0..1

    int buf = 0;
    int tile0 = blockIdx.x;
    if (tile0 < NTILES) loadTileDirect(smem, 0, e, tile0);
    __syncthreads();

    for (int tile = tile0; tile < NTILES; tile += gridDim.x) {
        const int ntile = tile + gridDim.x;
        const bool havenext = ntile < NTILES;

        // Prefetch next A-tile into registers (hidden under the mma loop).
        float4 pf[10];
        if (havenext) {
            const float4* src = (const float4*)(e + (size_t)ntile * TROWS * HH);
            #pragma unroll
            for (int q = 0; q < 5; q++) {
                int ch = tid + 256 * q;
                pf[2 * q]     = src[ch * 2];
                pf[2 * q + 1] = src[ch * 2 + 1];
            }
        }
        if (tid < TROWS) sIdx[tid] = edge_index[(size_t)tile * TROWS + tid];

        // ---- MMA mainloop: D[80 x 128] over K=128, 3-term bf16 split ----
        float acc[5][2][4];
        #pragma unroll
        for (int mt = 0; mt < 5; mt++)
            #pragma unroll
            for (int nt = 0; nt < 2; nt++)
                #pragma unroll
                for (int q = 0; q < 4; q++) acc[mt][nt][q] = 0.f;

        const uint32_t baseA  = sb + SA_OFF + buf * ABUF_B;
        const uint32_t baseAl = baseA + ALO;
        #pragma unroll
        for (int ks = 0; ks < 8; ks++) {
            uint32_t bh[4], bl[4];
            {
                int row = ks * 16 + lrow;
                int ch = w * 2 + lchk;
                uint32_t off = ((uint32_t)row << 8) + (((uint32_t)(ch ^ (row & 7))) << 4);
                ldsm4t(sb + SWH_OFF + off, bh);
                ldsm4t(sb + SWL_OFF + off, bl);
            }
            uint32_t ah[5][4];
            #pragma unroll
            for (int mt = 0; mt < 5; mt++) {
                int row = mt * 16 + lrow;
                int ch = ks * 2 + lchk;
                uint32_t off = ((uint32_t)row << 8) + (((uint32_t)(ch ^ (row & 7))) << 4);
                ldsm4(baseA + off, ah[mt]);
            }
            #pragma unroll
            for (int mt = 0; mt < 5; mt++) {
                mma16816(acc[mt][0], ah[mt], bh[0], bh[1]);   // eh*wh
                mma16816(acc[mt][1], ah[mt], bh[2], bh[3]);
                mma16816(acc[mt][0], ah[mt], bl[0], bl[1]);   // eh*wl
                mma16816(acc[mt][1], ah[mt], bl[2], bl[3]);
            }
            uint32_t al[5][4];
            #pragma unroll
            for (int mt = 0; mt < 5; mt++) {
                int row = mt * 16 + lrow;
                int ch = ks * 2 + lchk;
                uint32_t off = ((uint32_t)row << 8) + (((uint32_t)(ch ^ (row & 7))) << 4);
                ldsm4(baseAl + off, al[mt]);
            }
            #pragma unroll
            for (int mt = 0; mt < 5; mt++) {
                mma16816(acc[mt][0], al[mt], bh[0], bh[1]);   // el*wh
                mma16816(acc[mt][1], al[mt], bh[2], bh[3]);
            }
        }

        // ---- D fragments -> logits smem ----
        #pragma unroll
        for (int mt = 0; mt < 5; mt++)
            #pragma unroll
            for (int nt = 0; nt < 2; nt++) {
                int r0 = mt * 16 + (l >> 2);
                int c0 = w * 16 + nt * 8 + 2 * (l & 3);
                *(float2*)(sLog + r0 * LSTRIDE + c0) =
                    make_float2(acc[mt][nt][0], acc[mt][nt][1]);
                *(float2*)(sLog + (r0 + 8) * LSTRIDE + c0) =
                    make_float2(acc[mt][nt][2], acc[mt][nt][3]);
            }

        // ---- Store prefetched next tile into the other buffer ----
        if (havenext) {
            #pragma unroll
            for (int q = 0; q < 5; q++)
                cvtStoreA(smem, buf ^ 1, tid + 256 * q, pf[2 * q], pf[2 * q + 1]);
        }
        __syncthreads();

        // ---- Epilogue: softmax over 20 edges per (node, channel) + gather ----
        {
            const int j = tid & 127;
            #pragma unroll
            for (int tt = (tid >> 7); tt < TNODES; tt += 2) {
                float L[EE];
                #pragma unroll
                for (int i = 0; i < EE; i++)
                    L[i] = sLog[(tt * EE + i) * LSTRIDE + j];
                float m = L[0];
                #pragma unroll
                for (int i = 1; i < EE; i++) m = fmaxf(m, L[i]);
                float s = 0.f;
                #pragma unroll
                for (int i = 0; i < EE; i++) {
                    float ex = __expf(L[i] - m);
                    L[i] = ex;
                    s += ex;
                }
                const int node = tile * TNODES + tt;
                const int bbase = (node / NN) * NN;
                float accO = 0.f;
                #pragma unroll
                for (int i = 0; i < EE; i++) {
                    int rr = sIdx[tt * EE + i];
                    accO += L[i] * g_Vx[(size_t)(bbase + rr) * HH + j];
                }
                out[(size_t)node * HH + j] += accO * __fdividef(1.f, s);
            }
        }
        __syncthreads();
        buf ^= 1;
    }
}

// ---------------------------------------------------------------------------
extern "C" void kernel_launch(void* const* d_in, const int* in_sizes, int n_in,
                              void* d_out, int out_size)
{
    const float* x          = (const float*)d_in[0];
    const float* e          = (const float*)d_in[1];
    const float* Wu         = (const float*)d_in[2];
    const float* bu         = (const float*)d_in[3];
    const float* Wv         = (const float*)d_in[4];
    const float* bv         = (const float*)d_in[5];
    const float* We         = (const float*)d_in[6];
    const int*   edge_index = (const int*)d_in[8];
    float* out = (float*)d_out;

    int sms = 148;
    cudaDeviceGetAttribute(&sms, cudaDevAttrMultiProcessorCount, 0);

    const int smemA = (16384 + 16384 + 2048) * 4;   // 139264 B
    cudaFuncSetAttribute(kA, cudaFuncAttributeMaxDynamicSharedMemorySize, smemA);
    cudaFuncSetAttribute(kB, cudaFuncAttributeMaxDynamicSharedMemorySize, SMEMB);

    kA<<<sms, 256, smemA>>>(x, Wu, bu, Wv, bv, out);
    kB<<<sms, 256, SMEMB>>>(e, We, edge_index, out);
}